// round 14
// baseline (speedup 1.0000x reference)
#include <cuda_runtime.h>
#include <cstdint>

#define B_ 4096
#define L_ 200
#define E_ 128
#define A_ 128
#define ROWB 272            // bytes per bf16 row (17 x 16B -> conflict-free ldmatrix)
#define ROWU 68             // uint32 per row

// dynamic smem layout (main kernel)
#define OFF_AS 0                         // bf16 As[208][136] = 56576 B
#define OFF_BS 56576                     // bf16 Bs[128][136] = 34816 B (Wc, then W2T)
#define OFF_MS 91392
struct Misc {
    float qwv[A_], b2v[A_], w3v[A_];
    uint32_t qb[64];
    float scores[256], wts[256];
    float red[16], po[256];
};
#define SMEM_TOTAL (OFF_MS + (int)sizeof(Misc))   // ~96.3 KB -> 2 CTAs/SM

// Global scratch (allocation forbidden)
__device__ float    g_qw[B_ * A_];       // q @ (W1q + W1d) + b1
__device__ float    g_W1c[E_ * A_];      // W1q + W1d   [e][a]
__device__ uint32_t g_Wkb[A_ * 64];      // bf16x2 (W1k - W1d)^T pairs [a][e/2]
__device__ uint32_t g_Wmb[A_ * 64];      // bf16x2 W1m^T pairs         [a][e/2]
__device__ uint32_t g_W2Tb[A_ * A_ / 2]; // W2^T bf16 pairs [aout][ain/2]

__device__ __forceinline__ uint32_t smem_u32(const void* p) {
    uint32_t a;
    asm("{ .reg .u64 t; cvta.to.shared.u64 t, %1; cvt.u32.u64 %0, t; }"
        : "=r"(a) : "l"(p));
    return a;
}
__device__ __forceinline__ uint32_t bfpack(float lo, float hi) {
    uint32_t r;
    asm("cvt.rn.bf16x2.f32 %0, %1, %2;" : "=r"(r) : "f"(hi), "f"(lo));
    return r;
}
__device__ __forceinline__ uint32_t bffma2(uint32_t a, uint32_t b, uint32_t c) {
    uint32_t d;
    asm("fma.rn.bf16x2 %0, %1, %2, %3;" : "=r"(d) : "r"(a), "r"(b), "r"(c));
    return d;
}
#define LDSM4(r, addr)                                                         \
    asm volatile("ldmatrix.sync.aligned.m8n8.x4.shared.b16 {%0,%1,%2,%3}, [%4];" \
                 : "=r"((r)[0]), "=r"((r)[1]), "=r"((r)[2]), "=r"((r)[3])      \
                 : "r"(addr))
#define MMAB(d, a, b0, b1)                                                     \
    asm volatile("mma.sync.aligned.m16n8k16.row.col.f32.bf16.bf16.f32 "        \
                 "{%0,%1,%2,%3}, {%4,%5,%6,%7}, {%8,%9}, {%0,%1,%2,%3};"       \
                 : "+f"((d)[0]), "+f"((d)[1]), "+f"((d)[2]), "+f"((d)[3])      \
                 : "r"((a)[0]), "r"((a)[1]), "r"((a)[2]), "r"((a)[3]),         \
                   "r"(b0), "r"(b1))

// ---------------- prep kernels (split form, measured best) ----------------
__global__ void prep_wt(const float* __restrict__ W1, const float* __restrict__ W2) {
    int idx = blockIdx.x * blockDim.x + threadIdx.x;
    if (idx < A_ * E_) {
        g_W1c[idx] = W1[idx] + W1[2 * E_ * A_ + idx];
    }
    if (idx < A_ * 64) {
        int a = idx >> 6, p = idx & 63, e = 2 * p;
        float wk0 = W1[(E_ + e) * A_ + a]     - W1[(2 * E_ + e) * A_ + a];
        float wk1 = W1[(E_ + e + 1) * A_ + a] - W1[(2 * E_ + e + 1) * A_ + a];
        g_Wkb[idx] = bfpack(wk0, wk1);
        g_Wmb[idx] = bfpack(W1[(3 * E_ + e) * A_ + a],
                            W1[(3 * E_ + e + 1) * A_ + a]);
    }
    if (idx < A_ * A_ / 2) {
        int a = idx >> 6, p = idx & 63, e = 2 * p;
        g_W2Tb[idx] = bfpack(W2[e * A_ + a], W2[(e + 1) * A_ + a]);
    }
}

__global__ __launch_bounds__(256) void prep_qw2(const float* __restrict__ query,
                                                const float* __restrict__ b1) {
    extern __shared__ float w[];               // [E_][A_]
    __shared__ float qsh[32 * E_];
    int b0 = blockIdx.x * 32;
    for (int i = threadIdx.x; i < E_ * A_ / 4; i += 256)
        ((float4*)w)[i] = ((const float4*)g_W1c)[i];
    for (int i = threadIdx.x; i < 32 * E_ / 4; i += 256)
        ((float4*)qsh)[i] = ((const float4*)(query + (size_t)b0 * E_))[i];
    __syncthreads();
    int r = threadIdx.x >> 3;
    int a0 = (threadIdx.x & 7) * 4;
    float acc[4][4];
#pragma unroll
    for (int j = 0; j < 4; j++)
#pragma unroll
        for (int i = 0; i < 4; i++) acc[j][i] = b1[a0 + 32 * j + i];
#pragma unroll 4
    for (int e = 0; e < E_; e++) {
        float qv = qsh[r * E_ + e];
#pragma unroll
        for (int j = 0; j < 4; j++) {
            float4 wv = *(const float4*)&w[e * A_ + a0 + 32 * j];
            acc[j][0] = fmaf(qv, wv.x, acc[j][0]);
            acc[j][1] = fmaf(qv, wv.y, acc[j][1]);
            acc[j][2] = fmaf(qv, wv.z, acc[j][2]);
            acc[j][3] = fmaf(qv, wv.w, acc[j][3]);
        }
    }
#pragma unroll
    for (int j = 0; j < 4; j++)
        *(float4*)&g_qw[(size_t)(b0 + r) * A_ + a0 + 32 * j] =
            make_float4(acc[j][0], acc[j][1], acc[j][2], acc[j][3]);
}

// ---------------- warp GEMM bodies (one 16-row slab each; proven form) ------
__device__ __forceinline__ void gemm1_slab(uint32_t AsU, uint32_t BsU,
                                           const float* __restrict__ qwv,
                                           int rowbase, int lane,
                                           uint32_t h1f[8][4]) {
    const int tig = lane & 3;
    const uint32_t aAddr = AsU +
        (uint32_t)((rowbase + (lane & 15)) * ROWB + (lane >> 4) * 16);
    const int bRow = ((lane >> 4) << 3) + (lane & 7);
    const uint32_t bAddr = BsU + (uint32_t)(bRow * ROWB + ((lane >> 3) & 1) * 16);
#pragma unroll
    for (int qh = 0; qh < 4; qh++) {
        float acc[4][4];
#pragma unroll
        for (int nt = 0; nt < 4; nt++)
#pragma unroll
            for (int j = 0; j < 4; j++) acc[nt][j] = 0.f;
#pragma unroll
        for (int kc = 0; kc < 8; kc++) {
            uint32_t a[4];
            LDSM4(a, aAddr + kc * 32);
#pragma unroll
            for (int npl = 0; npl < 2; npl++) {
                uint32_t bf[4];
                LDSM4(bf, bAddr + (qh * 32 + npl * 16) * ROWB + kc * 32);
                MMAB(acc[2 * npl],     a, bf[0], bf[1]);
                MMAB(acc[2 * npl + 1], a, bf[2], bf[3]);
            }
        }
#pragma unroll
        for (int ntl = 0; ntl < 4; ntl++) {
            int ntg = qh * 4 + ntl;
            int c0 = ntg * 8 + 2 * tig;
            float q0 = qwv[c0], q1 = qwv[c0 + 1];
            int kcg = ntg >> 1, hf = (ntg & 1) << 1;
            h1f[kcg][hf] =
                bfpack(fmaxf(acc[ntl][0] + q0, 0.f), fmaxf(acc[ntl][1] + q1, 0.f));
            h1f[kcg][hf + 1] =
                bfpack(fmaxf(acc[ntl][2] + q0, 0.f), fmaxf(acc[ntl][3] + q1, 0.f));
        }
    }
}

__device__ __forceinline__ void gemm2_slab(uint32_t BsU, const float* __restrict__ b2v,
                                           const float* __restrict__ w3v, int lane,
                                           uint32_t h1f[8][4], float rs[2]) {
    const int tig = lane & 3;
    const int bRow = ((lane >> 4) << 3) + (lane & 7);
    const uint32_t bAddr = BsU + (uint32_t)(bRow * ROWB + ((lane >> 3) & 1) * 16);
#pragma unroll
    for (int qh = 0; qh < 4; qh++) {
        float acc[4][4];
#pragma unroll
        for (int nt = 0; nt < 4; nt++)
#pragma unroll
            for (int j = 0; j < 4; j++) acc[nt][j] = 0.f;
#pragma unroll
        for (int kc = 0; kc < 8; kc++) {
#pragma unroll
            for (int npl = 0; npl < 2; npl++) {
                uint32_t bf[4];
                LDSM4(bf, bAddr + (qh * 32 + npl * 16) * ROWB + kc * 32);
                MMAB(acc[2 * npl],     h1f[kc], bf[0], bf[1]);
                MMAB(acc[2 * npl + 1], h1f[kc], bf[2], bf[3]);
            }
        }
#pragma unroll
        for (int ntl = 0; ntl < 4; ntl++) {
            int c0 = qh * 32 + ntl * 8 + 2 * tig;
            float b20 = b2v[c0], b21 = b2v[c0 + 1];
            float w30 = w3v[c0], w31 = w3v[c0 + 1];
            rs[0] = fmaf(fmaxf(acc[ntl][0] + b20, 0.f), w30,
                    fmaf(fmaxf(acc[ntl][1] + b21, 0.f), w31, rs[0]));
            rs[1] = fmaf(fmaxf(acc[ntl][2] + b20, 0.f), w30,
                    fmaf(fmaxf(acc[ntl][3] + b21, 0.f), w31, rs[1]));
        }
    }
}

// ---------------- main kernel ----------------
__global__ __launch_bounds__(256, 2) void din_main(
    const float* __restrict__ query,
    const float* __restrict__ keys,
    const void*  __restrict__ len_ptr,
    const float* __restrict__ pos,
    const float* __restrict__ b2,
    const float* __restrict__ W3,
    const float* __restrict__ b3,
    float* __restrict__ out)
{
    extern __shared__ char sm[];
    uint32_t* As32 = (uint32_t*)(sm + OFF_AS);
    uint32_t* Bs32 = (uint32_t*)(sm + OFF_BS);
    Misc*     m    = (Misc*)(sm + OFF_MS);
    const uint32_t AsU = smem_u32(sm + OFF_AS);
    const uint32_t BsU = smem_u32(sm + OFF_BS);

    const int b = blockIdx.x;
    const int tid = threadIdx.x;
    const int wid = tid >> 5;
    const int lane = tid & 31;
    const int g = lane >> 2;
    const int tig = lane & 3;

    // keys_length dtype sniff (values in [1, L])
    unsigned long long first8 = *(const unsigned long long*)len_ptr;
    int len = (first8 <= (unsigned long long)L_)
            ? (int)((const long long*)len_ptr)[b]
            : ((const int*)len_ptr)[b];
    const int nsl = (len + 15) >> 4;

    if (tid < 128) {
        m->qwv[tid] = g_qw[(size_t)b * A_ + tid];
        m->b2v[tid] = b2[tid];
        m->w3v[tid] = W3[tid];
    }
    if (tid < 64) {
        float2 qf = ((const float2*)query)[(size_t)b * 64 + tid];
        m->qb[tid] = bfpack(qf.x, qf.y);
    }
    __syncthreads();

    // ---- build As = bf16(keys+pos) for valid rows only ----
    {
        const float4* k4 = (const float4*)(keys + (size_t)b * L_ * E_);
        const float4* p4 = (const float4*)pos;
        for (int idx = tid; idx < len * 32; idx += 256) {
            int l = idx >> 5, c4 = idx & 31, e0 = c4 * 4;
            float4 kv = k4[l * 32 + c4], pv = p4[l * 32 + c4];
            uint2 r;
            r.x = bfpack(kv.x + pv.x, kv.y + pv.y);
            r.y = bfpack(kv.z + pv.z, kv.w + pv.w);
            *(uint2*)&As32[l * ROWU + (e0 >> 1)] = r;
        }
        const uint2* wk2 = (const uint2*)g_Wkb;
        const uint2* wm2 = (const uint2*)g_Wmb;
        const uint2* qb2 = (const uint2*)m->qb;
        for (int idx = tid; idx < 128 * 32; idx += 256) {
            int a = idx >> 5, u2 = idx & 31;
            uint2 wk = wk2[a * 32 + u2];
            uint2 wm = wm2[a * 32 + u2];
            uint2 qq = qb2[u2];
            uint2 r;
            r.x = bffma2(qq.x, wm.x, wk.x);
            r.y = bffma2(qq.y, wm.y, wk.y);
            *(uint2*)&Bs32[a * ROWU + 2 * u2] = r;
        }
    }
    __syncthreads();

    // ---- prefetch W2T into registers (L2 latency overlaps GEMM1) ----
    uint4 w2t[8];
    {
        const uint4* src = (const uint4*)g_W2Tb;
#pragma unroll
        for (int j = 0; j < 8; j++)
            w2t[j] = __ldg(&src[tid + j * 256]);
    }

    // ---- GEMM1 over active slabs only (warp w owns slabs w and w+8) ----
    uint32_t h1f[2][8][4];
    const int s0 = wid, s1 = wid + 8;
    if (s0 < nsl) gemm1_slab(AsU, BsU, m->qwv, s0 * 16, lane, h1f[0]);
    if (s1 < nsl) gemm1_slab(AsU, BsU, m->qwv, s1 * 16, lane, h1f[1]);
    __syncthreads();                     // all warps done reading Bs (Wc)

    // store prefetched W2T into Bs (pure STS; w2t registers die here)
    {
        uint4* dst = (uint4*)Bs32;
#pragma unroll
        for (int j = 0; j < 8; j++) {
            int idx = tid + j * 256;
            int row = idx >> 4, c = idx & 15;
            dst[row * 17 + c] = w2t[j];
        }
    }
    __syncthreads();

    // ---- GEMM2 + score epilogue over active slabs (per-slab, reg-safe) ----
    {
        float rs[4] = {0.f, 0.f, 0.f, 0.f};
        if (s0 < nsl) gemm2_slab(BsU, m->b2v, m->w3v, lane, h1f[0], rs);
        if (s1 < nsl) gemm2_slab(BsU, m->b2v, m->w3v, lane, h1f[1], rs + 2);
#pragma unroll
        for (int i = 0; i < 4; i++) {
            rs[i] += __shfl_xor_sync(0xffffffffu, rs[i], 1);
            rs[i] += __shfl_xor_sync(0xffffffffu, rs[i], 2);
        }
        if (tig == 0) {
            float b3v = b3[0];
            if (s0 < nsl) {
                m->scores[s0 * 16 + g]     = rs[0] + b3v;
                m->scores[s0 * 16 + 8 + g] = rs[1] + b3v;
            }
            if (s1 < nsl) {
                m->scores[s1 * 16 + g]     = rs[2] + b3v;
                m->scores[s1 * 16 + 8 + g] = rs[3] + b3v;
            }
        }
    }

    // ---- final-sum setup + prefetch of first 8 key rows (overlaps softmax) --
    const int e_fs = tid & 127, half_fs = tid >> 7;
    const float* kb = keys + (size_t)b * L_ * E_ + e_fs;
    const float* pb = pos + e_fs;
    const int mid_fs = (len + 1) >> 1;
    const int l0_fs = half_fs ? mid_fs : 0;
    const int l1_fs = half_fs ? len : mid_fs;
    float kpre[8];
#pragma unroll
    for (int i = 0; i < 8; i++) {
        int li = l0_fs + i;
        kpre[i] = (li < l1_fs)
                ? __ldg(&kb[(size_t)li * E_]) + pb[(size_t)li * E_]
                : 0.f;
    }
    __syncthreads();

    // ---- softmax over valid l ----
    {
        int l = tid;
        bool valid = l < len;
        float sc = valid ? m->scores[l] : -1e30f;
        float mx = sc;
#pragma unroll
        for (int off = 16; off >= 1; off >>= 1)
            mx = fmaxf(mx, __shfl_xor_sync(0xffffffffu, mx, off));
        if (lane == 0) m->red[wid] = mx;
        __syncthreads();
        float M = m->red[0];
#pragma unroll
        for (int i = 1; i < 8; i++) M = fmaxf(M, m->red[i]);
        float w = valid ? __expf(sc - M) : 0.f;
        float sum = w;
#pragma unroll
        for (int off = 16; off >= 1; off >>= 1)
            sum += __shfl_xor_sync(0xffffffffu, sum, off);
        if (lane == 0) m->red[8 + wid] = sum;
        __syncthreads();
        float S = 0.f;
#pragma unroll
        for (int i = 0; i < 8; i++) S += m->red[8 + i];
        m->wts[l] = w / S;
    }
    __syncthreads();

    // ---- out[e] = sum_{l<len} wts[l] * (keys[b][l][e] + pos[l][e]) ----
    //      first 8 rows come from the pre-softmax register prefetch;
    //      8 independent accumulator chains hide the remaining L2 latency.
    {
        float a[8];
#pragma unroll
        for (int i = 0; i < 8; i++) {
            int li = l0_fs + i;
            a[i] = (li < l1_fs) ? m->wts[li] * kpre[i] : 0.f;
        }
        int l = l0_fs + 8;
        for (; l + 7 < l1_fs; l += 8) {
#pragma unroll
            for (int i = 0; i < 8; i++)
                a[i] = fmaf(m->wts[l + i],
                            __ldg(&kb[(size_t)(l + i) * E_]) + pb[(size_t)(l + i) * E_],
                            a[i]);
        }
        for (int i = 0; l < l1_fs; l++, i++)
            a[i] = fmaf(m->wts[l], __ldg(&kb[(size_t)l * E_]) + pb[(size_t)l * E_], a[i]);
        float r = ((a[0] + a[1]) + (a[2] + a[3])) + ((a[4] + a[5]) + (a[6] + a[7]));
        m->po[half_fs * 128 + e_fs] = r;
    }
    __syncthreads();
    if (tid < 128)
        out[(size_t)b * E_ + tid] = m->po[tid] + m->po[128 + tid];
}

// ---------------- entry ----------------
extern "C" void kernel_launch(void* const* d_in, const int* in_sizes, int n_in,
                              void* d_out, int out_size) {
    const float* query = (const float*)d_in[0];
    const float* keys  = (const float*)d_in[1];
    const void*  klen  = d_in[2];
    const float* pos   = (const float*)d_in[3];
    const float* W1    = (const float*)d_in[4];
    const float* b1    = (const float*)d_in[5];
    const float* W2    = (const float*)d_in[6];
    const float* b2    = (const float*)d_in[7];
    const float* W3    = (const float*)d_in[8];
    const float* b3    = (const float*)d_in[9];
    float* out = (float*)d_out;
    (void)in_sizes; (void)n_in; (void)out_size;

    cudaFuncSetAttribute(din_main, cudaFuncAttributeMaxDynamicSharedMemorySize,
                         SMEM_TOTAL);
    cudaFuncSetAttribute(prep_qw2, cudaFuncAttributeMaxDynamicSharedMemorySize,
                         E_ * A_ * 4);

    prep_wt<<<(A_ * E_ + 255) / 256, 256>>>(W1, W2);
    prep_qw2<<<B_ / 32, 256, E_ * A_ * 4>>>(query, b1);
    din_main<<<B_, 256, SMEM_TOTAL>>>(query, keys, klen, pos, b2, W3, b3, out);
}

// round 15
// speedup vs baseline: 1.0061x; 1.0061x over previous
#include <cuda_runtime.h>
#include <cstdint>

#define B_ 4096
#define L_ 200
#define E_ 128
#define A_ 128
#define ROWB 272            // bytes per bf16 row (17 x 16B -> conflict-free ldmatrix)
#define ROWU 68             // uint32 per row

// dynamic smem layout (main kernel)
#define OFF_AS 0                         // bf16 As[208][136] = 56576 B
#define OFF_BS 56576                     // bf16 Bs[128][136] = 34816 B (Wc, then W2T)
#define OFF_MS 91392
struct Misc {
    float qwv[A_], b2v[A_], w3v[A_];
    uint32_t qb[64];
    float scores[256], wts[256];
    float red[16], po[256];
};
#define SMEM_TOTAL (OFF_MS + (int)sizeof(Misc))   // ~96.3 KB -> 2 CTAs/SM

// Global scratch (allocation forbidden)
__device__ float    g_qw[B_ * A_];       // q @ (W1q + W1d) + b1
__device__ float    g_W1c[E_ * A_];      // W1q + W1d   [e][a]
__device__ uint32_t g_Wkb[A_ * 64];      // bf16x2 (W1k - W1d)^T pairs [a][e/2]
__device__ uint32_t g_Wmb[A_ * 64];      // bf16x2 W1m^T pairs         [a][e/2]
__device__ uint32_t g_W2Tb[A_ * A_ / 2]; // W2^T bf16 pairs [aout][ain/2]

__device__ __forceinline__ uint32_t smem_u32(const void* p) {
    uint32_t a;
    asm("{ .reg .u64 t; cvta.to.shared.u64 t, %1; cvt.u32.u64 %0, t; }"
        : "=r"(a) : "l"(p));
    return a;
}
__device__ __forceinline__ uint32_t bfpack(float lo, float hi) {
    uint32_t r;
    asm("cvt.rn.bf16x2.f32 %0, %1, %2;" : "=r"(r) : "f"(hi), "f"(lo));
    return r;
}
__device__ __forceinline__ uint32_t bffma2(uint32_t a, uint32_t b, uint32_t c) {
    uint32_t d;
    asm("fma.rn.bf16x2 %0, %1, %2, %3;" : "=r"(d) : "r"(a), "r"(b), "r"(c));
    return d;
}
#define LDSM4(r, addr)                                                         \
    asm volatile("ldmatrix.sync.aligned.m8n8.x4.shared.b16 {%0,%1,%2,%3}, [%4];" \
                 : "=r"((r)[0]), "=r"((r)[1]), "=r"((r)[2]), "=r"((r)[3])      \
                 : "r"(addr))
#define MMAB(d, a, b0, b1)                                                     \
    asm volatile("mma.sync.aligned.m16n8k16.row.col.f32.bf16.bf16.f32 "        \
                 "{%0,%1,%2,%3}, {%4,%5,%6,%7}, {%8,%9}, {%0,%1,%2,%3};"       \
                 : "+f"((d)[0]), "+f"((d)[1]), "+f"((d)[2]), "+f"((d)[3])      \
                 : "r"((a)[0]), "r"((a)[1]), "r"((a)[2]), "r"((a)[3]),         \
                   "r"(b0), "r"(b1))

// ---------------- prep kernels (split form, measured best) ----------------
__global__ void prep_wt(const float* __restrict__ W1, const float* __restrict__ W2) {
    int idx = blockIdx.x * blockDim.x + threadIdx.x;
    if (idx < A_ * E_) {
        g_W1c[idx] = W1[idx] + W1[2 * E_ * A_ + idx];
    }
    if (idx < A_ * 64) {
        int a = idx >> 6, p = idx & 63, e = 2 * p;
        float wk0 = W1[(E_ + e) * A_ + a]     - W1[(2 * E_ + e) * A_ + a];
        float wk1 = W1[(E_ + e + 1) * A_ + a] - W1[(2 * E_ + e + 1) * A_ + a];
        g_Wkb[idx] = bfpack(wk0, wk1);
        g_Wmb[idx] = bfpack(W1[(3 * E_ + e) * A_ + a],
                            W1[(3 * E_ + e + 1) * A_ + a]);
    }
    if (idx < A_ * A_ / 2) {
        int a = idx >> 6, p = idx & 63, e = 2 * p;
        g_W2Tb[idx] = bfpack(W2[e * A_ + a], W2[(e + 1) * A_ + a]);
    }
}

__global__ __launch_bounds__(256) void prep_qw2(const float* __restrict__ query,
                                                const float* __restrict__ b1) {
    extern __shared__ float w[];               // [E_][A_]
    __shared__ float qsh[32 * E_];
    int b0 = blockIdx.x * 32;
    for (int i = threadIdx.x; i < E_ * A_ / 4; i += 256)
        ((float4*)w)[i] = ((const float4*)g_W1c)[i];
    for (int i = threadIdx.x; i < 32 * E_ / 4; i += 256)
        ((float4*)qsh)[i] = ((const float4*)(query + (size_t)b0 * E_))[i];
    __syncthreads();
    int r = threadIdx.x >> 3;
    int a0 = (threadIdx.x & 7) * 4;
    float acc[4][4];
#pragma unroll
    for (int j = 0; j < 4; j++)
#pragma unroll
        for (int i = 0; i < 4; i++) acc[j][i] = b1[a0 + 32 * j + i];
#pragma unroll 4
    for (int e = 0; e < E_; e++) {
        float qv = qsh[r * E_ + e];
#pragma unroll
        for (int j = 0; j < 4; j++) {
            float4 wv = *(const float4*)&w[e * A_ + a0 + 32 * j];
            acc[j][0] = fmaf(qv, wv.x, acc[j][0]);
            acc[j][1] = fmaf(qv, wv.y, acc[j][1]);
            acc[j][2] = fmaf(qv, wv.z, acc[j][2]);
            acc[j][3] = fmaf(qv, wv.w, acc[j][3]);
        }
    }
#pragma unroll
    for (int j = 0; j < 4; j++)
        *(float4*)&g_qw[(size_t)(b0 + r) * A_ + a0 + 32 * j] =
            make_float4(acc[j][0], acc[j][1], acc[j][2], acc[j][3]);
}

// ---------------- fused warp GEMM bodies ----------------
// NM slabs: rows [rowbase, rowbase+16) and (NM==2) [rowbase+128, +16).
// B fragments shared across slabs -> B-LDSM halves for 2-slab warps.
template <int NM>
__device__ __forceinline__ void gemm1_t(uint32_t AsU, uint32_t BsU,
                                        const float* __restrict__ qwv,
                                        int rowbase, int lane,
                                        uint32_t h1f[][8][4]) {
    const int tig = lane & 3;
    uint32_t aAddr[NM];
    aAddr[0] = AsU + (uint32_t)((rowbase + (lane & 15)) * ROWB + (lane >> 4) * 16);
    if (NM == 2) aAddr[1] = aAddr[0] + 128 * ROWB;
    const int bRow = ((lane >> 4) << 3) + (lane & 7);
    const uint32_t bAddr = BsU + (uint32_t)(bRow * ROWB + ((lane >> 3) & 1) * 16);
#pragma unroll
    for (int qh = 0; qh < 4; qh++) {
        float acc[NM][4][4];
#pragma unroll
        for (int mt = 0; mt < NM; mt++)
#pragma unroll
            for (int nt = 0; nt < 4; nt++)
#pragma unroll
                for (int j = 0; j < 4; j++) acc[mt][nt][j] = 0.f;
#pragma unroll
        for (int kc = 0; kc < 8; kc++) {
            uint32_t a[NM][4];
#pragma unroll
            for (int mt = 0; mt < NM; mt++)
                LDSM4(a[mt], aAddr[mt] + kc * 32);
#pragma unroll
            for (int npl = 0; npl < 2; npl++) {
                uint32_t bf[4];
                LDSM4(bf, bAddr + (qh * 32 + npl * 16) * ROWB + kc * 32);
#pragma unroll
                for (int mt = 0; mt < NM; mt++) {
                    MMAB(acc[mt][2 * npl],     a[mt], bf[0], bf[1]);
                    MMAB(acc[mt][2 * npl + 1], a[mt], bf[2], bf[3]);
                }
            }
        }
#pragma unroll
        for (int mt = 0; mt < NM; mt++)
#pragma unroll
            for (int ntl = 0; ntl < 4; ntl++) {
                int ntg = qh * 4 + ntl;
                int c0 = ntg * 8 + 2 * tig;
                float q0 = qwv[c0], q1 = qwv[c0 + 1];
                int kcg = ntg >> 1, hf = (ntg & 1) << 1;
                h1f[mt][kcg][hf] =
                    bfpack(fmaxf(acc[mt][ntl][0] + q0, 0.f),
                           fmaxf(acc[mt][ntl][1] + q1, 0.f));
                h1f[mt][kcg][hf + 1] =
                    bfpack(fmaxf(acc[mt][ntl][2] + q0, 0.f),
                           fmaxf(acc[mt][ntl][3] + q1, 0.f));
            }
    }
}

template <int NM>
__device__ __forceinline__ void gemm2_t(uint32_t BsU, const float* __restrict__ b2v,
                                        const float* __restrict__ w3v, int lane,
                                        uint32_t h1f[][8][4], float rs[4]) {
    const int tig = lane & 3;
    const int bRow = ((lane >> 4) << 3) + (lane & 7);
    const uint32_t bAddr = BsU + (uint32_t)(bRow * ROWB + ((lane >> 3) & 1) * 16);
#pragma unroll
    for (int qh = 0; qh < 4; qh++) {
        float acc[NM][4][4];
#pragma unroll
        for (int mt = 0; mt < NM; mt++)
#pragma unroll
            for (int nt = 0; nt < 4; nt++)
#pragma unroll
                for (int j = 0; j < 4; j++) acc[mt][nt][j] = 0.f;
#pragma unroll
        for (int kc = 0; kc < 8; kc++) {
#pragma unroll
            for (int npl = 0; npl < 2; npl++) {
                uint32_t bf[4];
                LDSM4(bf, bAddr + (qh * 32 + npl * 16) * ROWB + kc * 32);
#pragma unroll
                for (int mt = 0; mt < NM; mt++) {
                    MMAB(acc[mt][2 * npl],     h1f[mt][kc], bf[0], bf[1]);
                    MMAB(acc[mt][2 * npl + 1], h1f[mt][kc], bf[2], bf[3]);
                }
            }
        }
#pragma unroll
        for (int mt = 0; mt < NM; mt++)
#pragma unroll
            for (int ntl = 0; ntl < 4; ntl++) {
                int c0 = qh * 32 + ntl * 8 + 2 * tig;
                float b20 = b2v[c0], b21 = b2v[c0 + 1];
                float w30 = w3v[c0], w31 = w3v[c0 + 1];
                rs[2 * mt + 0] = fmaf(fmaxf(acc[mt][ntl][0] + b20, 0.f), w30,
                                 fmaf(fmaxf(acc[mt][ntl][1] + b21, 0.f), w31, rs[2 * mt + 0]));
                rs[2 * mt + 1] = fmaf(fmaxf(acc[mt][ntl][2] + b20, 0.f), w30,
                                 fmaf(fmaxf(acc[mt][ntl][3] + b21, 0.f), w31, rs[2 * mt + 1]));
            }
    }
}

// ---------------- main kernel ----------------
__global__ __launch_bounds__(256, 2) void din_main(
    const float* __restrict__ query,
    const float* __restrict__ keys,
    const void*  __restrict__ len_ptr,
    const float* __restrict__ pos,
    const float* __restrict__ b2,
    const float* __restrict__ W3,
    const float* __restrict__ b3,
    float* __restrict__ out)
{
    extern __shared__ char sm[];
    uint32_t* As32 = (uint32_t*)(sm + OFF_AS);
    uint32_t* Bs32 = (uint32_t*)(sm + OFF_BS);
    Misc*     m    = (Misc*)(sm + OFF_MS);
    const uint32_t AsU = smem_u32(sm + OFF_AS);
    const uint32_t BsU = smem_u32(sm + OFF_BS);

    const int b = blockIdx.x;
    const int tid = threadIdx.x;
    const int wid = tid >> 5;
    const int lane = tid & 31;
    const int g = lane >> 2;
    const int tig = lane & 3;

    // keys_length dtype sniff (values in [1, L])
    unsigned long long first8 = *(const unsigned long long*)len_ptr;
    int len = (first8 <= (unsigned long long)L_)
            ? (int)((const long long*)len_ptr)[b]
            : ((const int*)len_ptr)[b];
    const int nsl = (len + 15) >> 4;

    if (tid < 128) {
        m->qwv[tid] = g_qw[(size_t)b * A_ + tid];
        m->b2v[tid] = b2[tid];
        m->w3v[tid] = W3[tid];
    }
    if (tid < 64) {
        float2 qf = ((const float2*)query)[(size_t)b * 64 + tid];
        m->qb[tid] = bfpack(qf.x, qf.y);
    }
    __syncthreads();

    // ---- build As = bf16(keys+pos) for valid rows only ----
    {
        const float4* k4 = (const float4*)(keys + (size_t)b * L_ * E_);
        const float4* p4 = (const float4*)pos;
        for (int idx = tid; idx < len * 32; idx += 256) {
            int l = idx >> 5, c4 = idx & 31, e0 = c4 * 4;
            float4 kv = k4[l * 32 + c4], pv = p4[l * 32 + c4];
            uint2 r;
            r.x = bfpack(kv.x + pv.x, kv.y + pv.y);
            r.y = bfpack(kv.z + pv.z, kv.w + pv.w);
            *(uint2*)&As32[l * ROWU + (e0 >> 1)] = r;
        }
        const uint2* wk2 = (const uint2*)g_Wkb;
        const uint2* wm2 = (const uint2*)g_Wmb;
        const uint2* qb2 = (const uint2*)m->qb;
        for (int idx = tid; idx < 128 * 32; idx += 256) {
            int a = idx >> 5, u2 = idx & 31;
            uint2 wk = wk2[a * 32 + u2];
            uint2 wm = wm2[a * 32 + u2];
            uint2 qq = qb2[u2];
            uint2 r;
            r.x = bffma2(qq.x, wm.x, wk.x);
            r.y = bffma2(qq.y, wm.y, wk.y);
            *(uint2*)&Bs32[a * ROWU + 2 * u2] = r;
        }
    }
    __syncthreads();

    // ---- GEMM1 fused over both slabs (shared B frags; NO w2t prefetch so
    //      registers stay under the 128 cap) ----
    uint32_t h1f[2][8][4];
    const int s0 = wid, s1 = wid + 8;
    if (s1 < nsl)      gemm1_t<2>(AsU, BsU, m->qwv, s0 * 16, lane, h1f);
    else if (s0 < nsl) gemm1_t<1>(AsU, BsU, m->qwv, s0 * 16, lane, h1f);
    __syncthreads();                     // all warps done reading Bs (Wc)

    // copy W2T (pre-packed bf16) into Bs straight from L2
    {
        const uint4* src = (const uint4*)g_W2Tb;
        uint4* dst = (uint4*)Bs32;
#pragma unroll
        for (int j = 0; j < 8; j++) {
            int idx = tid + j * 256;
            int row = idx >> 4, c = idx & 15;
            dst[row * 17 + c] = __ldg(&src[idx]);
        }
    }
    __syncthreads();

    // ---- GEMM2 fused over both slabs + score epilogue ----
    {
        float rs[4] = {0.f, 0.f, 0.f, 0.f};
        if (s1 < nsl)      gemm2_t<2>(BsU, m->b2v, m->w3v, lane, h1f, rs);
        else if (s0 < nsl) gemm2_t<1>(BsU, m->b2v, m->w3v, lane, h1f, rs);
#pragma unroll
        for (int i = 0; i < 4; i++) {
            rs[i] += __shfl_xor_sync(0xffffffffu, rs[i], 1);
            rs[i] += __shfl_xor_sync(0xffffffffu, rs[i], 2);
        }
        if (tig == 0) {
            float b3v = b3[0];
            if (s0 < nsl) {
                m->scores[s0 * 16 + g]     = rs[0] + b3v;
                m->scores[s0 * 16 + 8 + g] = rs[1] + b3v;
            }
            if (s1 < nsl) {
                m->scores[s1 * 16 + g]     = rs[2] + b3v;
                m->scores[s1 * 16 + 8 + g] = rs[3] + b3v;
            }
        }
    }
    __syncthreads();

    // ---- softmax over valid l ----
    {
        int l = tid;
        bool valid = l < len;
        float sc = valid ? m->scores[l] : -1e30f;
        float mx = sc;
#pragma unroll
        for (int off = 16; off >= 1; off >>= 1)
            mx = fmaxf(mx, __shfl_xor_sync(0xffffffffu, mx, off));
        if (lane == 0) m->red[wid] = mx;
        __syncthreads();
        float M = m->red[0];
#pragma unroll
        for (int i = 1; i < 8; i++) M = fmaxf(M, m->red[i]);
        float w = valid ? __expf(sc - M) : 0.f;
        float sum = w;
#pragma unroll
        for (int off = 16; off >= 1; off >>= 1)
            sum += __shfl_xor_sync(0xffffffffu, sum, off);
        if (lane == 0) m->red[8 + wid] = sum;
        __syncthreads();
        float S = 0.f;
#pragma unroll
        for (int i = 0; i < 8; i++) S += m->red[8 + i];
        m->wts[l] = __fdividef(w, S);
    }
    __syncthreads();

    // ---- out[e] = sum_{l<len} wts[l] * (keys[b][l][e] + pos[l][e]) ----
    {
        int e = tid & 127, half = tid >> 7;
        const float* kb = keys + (size_t)b * L_ * E_ + e;
        const float* pb = pos + e;
        int mid = (len + 1) >> 1;
        int l0 = half ? mid : 0;
        int l1 = half ? len : mid;
        float a0 = 0.f, a1 = 0.f, a2 = 0.f, a3 = 0.f;
        int l = l0;
        for (; l + 3 < l1; l += 4) {
            a0 = fmaf(m->wts[l],     __ldg(&kb[(size_t)l * E_])       + pb[(size_t)l * E_],       a0);
            a1 = fmaf(m->wts[l + 1], __ldg(&kb[(size_t)(l + 1) * E_]) + pb[(size_t)(l + 1) * E_], a1);
            a2 = fmaf(m->wts[l + 2], __ldg(&kb[(size_t)(l + 2) * E_]) + pb[(size_t)(l + 2) * E_], a2);
            a3 = fmaf(m->wts[l + 3], __ldg(&kb[(size_t)(l + 3) * E_]) + pb[(size_t)(l + 3) * E_], a3);
        }
        for (; l < l1; l++)
            a0 = fmaf(m->wts[l], __ldg(&kb[(size_t)l * E_]) + pb[(size_t)l * E_], a0);
        m->po[half * 128 + e] = (a0 + a1) + (a2 + a3);
    }
    __syncthreads();
    if (tid < 128)
        out[(size_t)b * E_ + tid] = m->po[tid] + m->po[128 + tid];
}

// ---------------- entry ----------------
extern "C" void kernel_launch(void* const* d_in, const int* in_sizes, int n_in,
                              void* d_out, int out_size) {
    const float* query = (const float*)d_in[0];
    const float* keys  = (const float*)d_in[1];
    const void*  klen  = d_in[2];
    const float* pos   = (const float*)d_in[3];
    const float* W1    = (const float*)d_in[4];
    const float* b1    = (const float*)d_in[5];
    const float* W2    = (const float*)d_in[6];
    const float* b2    = (const float*)d_in[7];
    const float* W3    = (const float*)d_in[8];
    const float* b3    = (const float*)d_in[9];
    float* out = (float*)d_out;
    (void)in_sizes; (void)n_in; (void)out_size;

    cudaFuncSetAttribute(din_main, cudaFuncAttributeMaxDynamicSharedMemorySize,
                         SMEM_TOTAL);
    cudaFuncSetAttribute(prep_qw2, cudaFuncAttributeMaxDynamicSharedMemorySize,
                         E_ * A_ * 4);

    prep_wt<<<(A_ * E_ + 255) / 256, 256>>>(W1, W2);
    prep_qw2<<<B_ / 32, 256, E_ * A_ * 4>>>(query, b1);
    din_main<<<B_, 256, SMEM_TOTAL>>>(query, keys, klen, pos, b2, W3, b3, out);
}

// round 16
// speedup vs baseline: 1.0405x; 1.0342x over previous
#include <cuda_runtime.h>
#include <cstdint>

#define B_ 4096
#define L_ 200
#define E_ 128
#define A_ 128
#define ROWB 272            // bytes per bf16 row (17 x 16B -> conflict-free ldmatrix)
#define ROWU 68             // uint32 per row

// dynamic smem layout (main kernel)
#define OFF_AS 0                         // bf16 As[208][136] = 56576 B
#define OFF_BS 56576                     // bf16 Bs[128][136] = 34816 B (Wc, then W2T)
#define OFF_MS 91392
struct Misc {
    float qwv[A_], b2v[A_], w3v[A_];
    uint32_t qb[64];
    float scores[256], wts[256];
    float red[16], po[256];
};
#define SMEM_TOTAL (OFF_MS + (int)sizeof(Misc))   // ~96.3 KB -> 2 CTAs/SM

// Global scratch (allocation forbidden)
__device__ float    g_qw[B_ * A_];       // q @ (W1q + W1d) + b1
__device__ float    g_W1c[E_ * A_];      // W1q + W1d   [e][a]
__device__ uint32_t g_Wkb[A_ * 64];      // bf16x2 (W1k - W1d)^T pairs [a][e/2]
__device__ uint32_t g_Wmb[A_ * 64];      // bf16x2 W1m^T pairs         [a][e/2]
__device__ uint32_t g_W2Tb[A_ * A_ / 2]; // W2^T bf16 pairs [aout][ain/2]

__device__ __forceinline__ uint32_t smem_u32(const void* p) {
    uint32_t a;
    asm("{ .reg .u64 t; cvta.to.shared.u64 t, %1; cvt.u32.u64 %0, t; }"
        : "=r"(a) : "l"(p));
    return a;
}
__device__ __forceinline__ uint32_t bfpack(float lo, float hi) {
    uint32_t r;
    asm("cvt.rn.bf16x2.f32 %0, %1, %2;" : "=r"(r) : "f"(hi), "f"(lo));
    return r;
}
__device__ __forceinline__ uint32_t bffma2(uint32_t a, uint32_t b, uint32_t c) {
    uint32_t d;
    asm("fma.rn.bf16x2 %0, %1, %2, %3;" : "=r"(d) : "r"(a), "r"(b), "r"(c));
    return d;
}
#define LDSM4(r, addr)                                                         \
    asm volatile("ldmatrix.sync.aligned.m8n8.x4.shared.b16 {%0,%1,%2,%3}, [%4];" \
                 : "=r"((r)[0]), "=r"((r)[1]), "=r"((r)[2]), "=r"((r)[3])      \
                 : "r"(addr))
#define MMAB(d, a, b0, b1)                                                     \
    asm volatile("mma.sync.aligned.m16n8k16.row.col.f32.bf16.bf16.f32 "        \
                 "{%0,%1,%2,%3}, {%4,%5,%6,%7}, {%8,%9}, {%0,%1,%2,%3};"       \
                 : "+f"((d)[0]), "+f"((d)[1]), "+f"((d)[2]), "+f"((d)[3])      \
                 : "r"((a)[0]), "r"((a)[1]), "r"((a)[2]), "r"((a)[3]),         \
                   "r"(b0), "r"(b1))

// ---------------- prep kernels ----------------
__global__ void prep_wt(const float* __restrict__ W1, const float* __restrict__ W2) {
    int idx = blockIdx.x * blockDim.x + threadIdx.x;
    if (idx < A_ * E_) {
        g_W1c[idx] = W1[idx] + W1[2 * E_ * A_ + idx];
    }
    if (idx < A_ * 64) {
        int a = idx >> 6, p = idx & 63, e = 2 * p;
        float wk0 = W1[(E_ + e) * A_ + a]     - W1[(2 * E_ + e) * A_ + a];
        float wk1 = W1[(E_ + e + 1) * A_ + a] - W1[(2 * E_ + e + 1) * A_ + a];
        g_Wkb[idx] = bfpack(wk0, wk1);
        g_Wmb[idx] = bfpack(W1[(3 * E_ + e) * A_ + a],
                            W1[(3 * E_ + e + 1) * A_ + a]);
    }
    if (idx < A_ * A_ / 2) {
        int a = idx >> 6, p = idx & 63, e = 2 * p;
        g_W2Tb[idx] = bfpack(W2[e * A_ + a], W2[(e + 1) * A_ + a]);
    }
}

// qw for 32 batch rows per block. Register-tiled 8 rows x 2 cols per thread:
// q loads are warp-uniform broadcasts, W1c read ONCE per block per thread-col.
// FMA order over e (ascending, seeded with b1) matches the old version exactly
// -> bitwise-identical g_qw.
__global__ __launch_bounds__(256) void prep_qw2(const float* __restrict__ query,
                                                const float* __restrict__ b1) {
    extern __shared__ float w[];               // [E_][A_]
    __shared__ float qsh[32 * E_];
    int b0 = blockIdx.x * 32;
    for (int i = threadIdx.x; i < E_ * A_ / 4; i += 256)
        ((float4*)w)[i] = ((const float4*)g_W1c)[i];
    for (int i = threadIdx.x; i < 32 * E_ / 4; i += 256)
        ((float4*)qsh)[i] = ((const float4*)(query + (size_t)b0 * E_))[i];
    __syncthreads();

    const int c2 = threadIdx.x & 63;           // column pair: cols 2c2, 2c2+1
    const int rg = threadIdx.x >> 6;           // row group: rows rg*8 .. rg*8+7
    const float2 bv = *(const float2*)&b1[2 * c2];

    float acc[8][2];
#pragma unroll
    for (int r = 0; r < 8; r++) { acc[r][0] = bv.x; acc[r][1] = bv.y; }

#pragma unroll 2
    for (int e0 = 0; e0 < E_; e0 += 4) {
        float4 q[8];
#pragma unroll
        for (int r = 0; r < 8; r++)
            q[r] = *(const float4*)&qsh[(rg * 8 + r) * E_ + e0];
#pragma unroll
        for (int k = 0; k < 4; k++) {
            float2 wv = *(const float2*)&w[(e0 + k) * A_ + 2 * c2];
#pragma unroll
            for (int r = 0; r < 8; r++) {
                float qv = (k == 0) ? q[r].x : (k == 1) ? q[r].y
                         : (k == 2) ? q[r].z : q[r].w;
                acc[r][0] = fmaf(qv, wv.x, acc[r][0]);
                acc[r][1] = fmaf(qv, wv.y, acc[r][1]);
            }
        }
    }
#pragma unroll
    for (int r = 0; r < 8; r++)
        *(float2*)&g_qw[(size_t)(b0 + rg * 8 + r) * A_ + 2 * c2] =
            make_float2(acc[r][0], acc[r][1]);
}

// ---------------- warp GEMM bodies (one 16-row slab each; proven best) ------
__device__ __forceinline__ void gemm1_slab(uint32_t AsU, uint32_t BsU,
                                           const float* __restrict__ qwv,
                                           int rowbase, int lane,
                                           uint32_t h1f[8][4]) {
    const int tig = lane & 3;
    const uint32_t aAddr = AsU +
        (uint32_t)((rowbase + (lane & 15)) * ROWB + (lane >> 4) * 16);
    const int bRow = ((lane >> 4) << 3) + (lane & 7);
    const uint32_t bAddr = BsU + (uint32_t)(bRow * ROWB + ((lane >> 3) & 1) * 16);
#pragma unroll
    for (int qh = 0; qh < 4; qh++) {
        float acc[4][4];
#pragma unroll
        for (int nt = 0; nt < 4; nt++)
#pragma unroll
            for (int j = 0; j < 4; j++) acc[nt][j] = 0.f;
#pragma unroll
        for (int kc = 0; kc < 8; kc++) {
            uint32_t a[4];
            LDSM4(a, aAddr + kc * 32);
#pragma unroll
            for (int npl = 0; npl < 2; npl++) {
                uint32_t bf[4];
                LDSM4(bf, bAddr + (qh * 32 + npl * 16) * ROWB + kc * 32);
                MMAB(acc[2 * npl],     a, bf[0], bf[1]);
                MMAB(acc[2 * npl + 1], a, bf[2], bf[3]);
            }
        }
#pragma unroll
        for (int ntl = 0; ntl < 4; ntl++) {
            int ntg = qh * 4 + ntl;
            int c0 = ntg * 8 + 2 * tig;
            float q0 = qwv[c0], q1 = qwv[c0 + 1];
            int kcg = ntg >> 1, hf = (ntg & 1) << 1;
            h1f[kcg][hf] =
                bfpack(fmaxf(acc[ntl][0] + q0, 0.f), fmaxf(acc[ntl][1] + q1, 0.f));
            h1f[kcg][hf + 1] =
                bfpack(fmaxf(acc[ntl][2] + q0, 0.f), fmaxf(acc[ntl][3] + q1, 0.f));
        }
    }
}

__device__ __forceinline__ void gemm2_slab(uint32_t BsU, const float* __restrict__ b2v,
                                           const float* __restrict__ w3v, int lane,
                                           uint32_t h1f[8][4], float rs[2]) {
    const int tig = lane & 3;
    const int bRow = ((lane >> 4) << 3) + (lane & 7);
    const uint32_t bAddr = BsU + (uint32_t)(bRow * ROWB + ((lane >> 3) & 1) * 16);
#pragma unroll
    for (int qh = 0; qh < 4; qh++) {
        float acc[4][4];
#pragma unroll
        for (int nt = 0; nt < 4; nt++)
#pragma unroll
            for (int j = 0; j < 4; j++) acc[nt][j] = 0.f;
#pragma unroll
        for (int kc = 0; kc < 8; kc++) {
#pragma unroll
            for (int npl = 0; npl < 2; npl++) {
                uint32_t bf[4];
                LDSM4(bf, bAddr + (qh * 32 + npl * 16) * ROWB + kc * 32);
                MMAB(acc[2 * npl],     h1f[kc], bf[0], bf[1]);
                MMAB(acc[2 * npl + 1], h1f[kc], bf[2], bf[3]);
            }
        }
#pragma unroll
        for (int ntl = 0; ntl < 4; ntl++) {
            int c0 = qh * 32 + ntl * 8 + 2 * tig;
            float b20 = b2v[c0], b21 = b2v[c0 + 1];
            float w30 = w3v[c0], w31 = w3v[c0 + 1];
            rs[0] = fmaf(fmaxf(acc[ntl][0] + b20, 0.f), w30,
                    fmaf(fmaxf(acc[ntl][1] + b21, 0.f), w31, rs[0]));
            rs[1] = fmaf(fmaxf(acc[ntl][2] + b20, 0.f), w30,
                    fmaf(fmaxf(acc[ntl][3] + b21, 0.f), w31, rs[1]));
        }
    }
}

// ---------------- main kernel (proven 243.8us body, untouched) --------------
__global__ __launch_bounds__(256, 2) void din_main(
    const float* __restrict__ query,
    const float* __restrict__ keys,
    const void*  __restrict__ len_ptr,
    const float* __restrict__ pos,
    const float* __restrict__ b2,
    const float* __restrict__ W3,
    const float* __restrict__ b3,
    float* __restrict__ out)
{
    extern __shared__ char sm[];
    uint32_t* As32 = (uint32_t*)(sm + OFF_AS);
    uint32_t* Bs32 = (uint32_t*)(sm + OFF_BS);
    Misc*     m    = (Misc*)(sm + OFF_MS);
    const uint32_t AsU = smem_u32(sm + OFF_AS);
    const uint32_t BsU = smem_u32(sm + OFF_BS);

    const int b = blockIdx.x;
    const int tid = threadIdx.x;
    const int wid = tid >> 5;
    const int lane = tid & 31;
    const int g = lane >> 2;
    const int tig = lane & 3;

    // keys_length dtype sniff (values in [1, L])
    unsigned long long first8 = *(const unsigned long long*)len_ptr;
    int len = (first8 <= (unsigned long long)L_)
            ? (int)((const long long*)len_ptr)[b]
            : ((const int*)len_ptr)[b];
    const int nsl = (len + 15) >> 4;

    if (tid < 128) {
        m->qwv[tid] = g_qw[(size_t)b * A_ + tid];
        m->b2v[tid] = b2[tid];
        m->w3v[tid] = W3[tid];
    }
    if (tid < 64) {
        float2 qf = ((const float2*)query)[(size_t)b * 64 + tid];
        m->qb[tid] = bfpack(qf.x, qf.y);
    }
    __syncthreads();

    // ---- build As = bf16(keys+pos) for valid rows only ----
    {
        const float4* k4 = (const float4*)(keys + (size_t)b * L_ * E_);
        const float4* p4 = (const float4*)pos;
        for (int idx = tid; idx < len * 32; idx += 256) {
            int l = idx >> 5, c4 = idx & 31, e0 = c4 * 4;
            float4 kv = k4[l * 32 + c4], pv = p4[l * 32 + c4];
            uint2 r;
            r.x = bfpack(kv.x + pv.x, kv.y + pv.y);
            r.y = bfpack(kv.z + pv.z, kv.w + pv.w);
            *(uint2*)&As32[l * ROWU + (e0 >> 1)] = r;
        }
        const uint2* wk2 = (const uint2*)g_Wkb;
        const uint2* wm2 = (const uint2*)g_Wmb;
        const uint2* qb2 = (const uint2*)m->qb;
        for (int idx = tid; idx < 128 * 32; idx += 256) {
            int a = idx >> 5, u2 = idx & 31;
            uint2 wk = wk2[a * 32 + u2];
            uint2 wm = wm2[a * 32 + u2];
            uint2 qq = qb2[u2];
            uint2 r;
            r.x = bffma2(qq.x, wm.x, wk.x);
            r.y = bffma2(qq.y, wm.y, wk.y);
            *(uint2*)&Bs32[a * ROWU + 2 * u2] = r;
        }
    }
    __syncthreads();

    // ---- prefetch W2T into registers (L2 latency overlaps GEMM1) ----
    uint4 w2t[8];
    {
        const uint4* src = (const uint4*)g_W2Tb;
#pragma unroll
        for (int j = 0; j < 8; j++)
            w2t[j] = __ldg(&src[tid + j * 256]);
    }

    // ---- GEMM1 over active slabs only (warp w owns slabs w and w+8) ----
    uint32_t h1f[2][8][4];
    const int s0 = wid, s1 = wid + 8;
    if (s0 < nsl) gemm1_slab(AsU, BsU, m->qwv, s0 * 16, lane, h1f[0]);
    if (s1 < nsl) gemm1_slab(AsU, BsU, m->qwv, s1 * 16, lane, h1f[1]);
    __syncthreads();                     // all warps done reading Bs (Wc)

    // store prefetched W2T into Bs (pure STS; w2t registers die here)
    {
        uint4* dst = (uint4*)Bs32;
#pragma unroll
        for (int j = 0; j < 8; j++) {
            int idx = tid + j * 256;
            int row = idx >> 4, c = idx & 15;
            dst[row * 17 + c] = w2t[j];
        }
    }
    __syncthreads();

    // ---- GEMM2 + score epilogue over active slabs (per-slab, reg-safe) ----
    {
        float rs[4] = {0.f, 0.f, 0.f, 0.f};
        if (s0 < nsl) gemm2_slab(BsU, m->b2v, m->w3v, lane, h1f[0], rs);
        if (s1 < nsl) gemm2_slab(BsU, m->b2v, m->w3v, lane, h1f[1], rs + 2);
#pragma unroll
        for (int i = 0; i < 4; i++) {
            rs[i] += __shfl_xor_sync(0xffffffffu, rs[i], 1);
            rs[i] += __shfl_xor_sync(0xffffffffu, rs[i], 2);
        }
        if (tig == 0) {
            float b3v = b3[0];
            if (s0 < nsl) {
                m->scores[s0 * 16 + g]     = rs[0] + b3v;
                m->scores[s0 * 16 + 8 + g] = rs[1] + b3v;
            }
            if (s1 < nsl) {
                m->scores[s1 * 16 + g]     = rs[2] + b3v;
                m->scores[s1 * 16 + 8 + g] = rs[3] + b3v;
            }
        }
    }
    __syncthreads();

    // ---- softmax over valid l ----
    {
        int l = tid;
        bool valid = l < len;
        float sc = valid ? m->scores[l] : -1e30f;
        float mx = sc;
#pragma unroll
        for (int off = 16; off >= 1; off >>= 1)
            mx = fmaxf(mx, __shfl_xor_sync(0xffffffffu, mx, off));
        if (lane == 0) m->red[wid] = mx;
        __syncthreads();
        float M = m->red[0];
#pragma unroll
        for (int i = 1; i < 8; i++) M = fmaxf(M, m->red[i]);
        float w = valid ? __expf(sc - M) : 0.f;
        float sum = w;
#pragma unroll
        for (int off = 16; off >= 1; off >>= 1)
            sum += __shfl_xor_sync(0xffffffffu, sum, off);
        if (lane == 0) m->red[8 + wid] = sum;
        __syncthreads();
        float S = 0.f;
#pragma unroll
        for (int i = 0; i < 8; i++) S += m->red[8 + i];
        m->wts[l] = w / S;
    }
    __syncthreads();

    // ---- out[e] = sum_{l<len} wts[l] * (keys[b][l][e] + pos[l][e]) ----
    {
        int e = tid & 127, half = tid >> 7;
        const float* kb = keys + (size_t)b * L_ * E_ + e;
        const float* pb = pos + e;
        int mid = (len + 1) >> 1;
        int l0 = half ? mid : 0;
        int l1 = half ? len : mid;
        float a0 = 0.f, a1 = 0.f, a2 = 0.f, a3 = 0.f;
        int l = l0;
        for (; l + 3 < l1; l += 4) {
            a0 = fmaf(m->wts[l],     __ldg(&kb[(size_t)l * E_])       + pb[(size_t)l * E_],       a0);
            a1 = fmaf(m->wts[l + 1], __ldg(&kb[(size_t)(l + 1) * E_]) + pb[(size_t)(l + 1) * E_], a1);
            a2 = fmaf(m->wts[l + 2], __ldg(&kb[(size_t)(l + 2) * E_]) + pb[(size_t)(l + 2) * E_], a2);
            a3 = fmaf(m->wts[l + 3], __ldg(&kb[(size_t)(l + 3) * E_]) + pb[(size_t)(l + 3) * E_], a3);
        }
        for (; l < l1; l++)
            a0 = fmaf(m->wts[l], __ldg(&kb[(size_t)l * E_]) + pb[(size_t)l * E_], a0);
        m->po[half * 128 + e] = (a0 + a1) + (a2 + a3);
    }
    __syncthreads();
    if (tid < 128)
        out[(size_t)b * E_ + tid] = m->po[tid] + m->po[128 + tid];
}

// ---------------- entry ----------------
extern "C" void kernel_launch(void* const* d_in, const int* in_sizes, int n_in,
                              void* d_out, int out_size) {
    const float* query = (const float*)d_in[0];
    const float* keys  = (const float*)d_in[1];
    const void*  klen  = d_in[2];
    const float* pos   = (const float*)d_in[3];
    const float* W1    = (const float*)d_in[4];
    const float* b1    = (const float*)d_in[5];
    const float* W2    = (const float*)d_in[6];
    const float* b2    = (const float*)d_in[7];
    const float* W3    = (const float*)d_in[8];
    const float* b3    = (const float*)d_in[9];
    float* out = (float*)d_out;
    (void)in_sizes; (void)n_in; (void)out_size;

    cudaFuncSetAttribute(din_main, cudaFuncAttributeMaxDynamicSharedMemorySize,
                         SMEM_TOTAL);
    cudaFuncSetAttribute(prep_qw2, cudaFuncAttributeMaxDynamicSharedMemorySize,
                         E_ * A_ * 4);

    prep_wt<<<(A_ * E_ + 255) / 256, 256>>>(W1, W2);
    prep_qw2<<<B_ / 32, 256, E_ * A_ * 4>>>(query, b1);
    din_main<<<B_, 256, SMEM_TOTAL>>>(query, keys, klen, pos, b2, W3, b3, out);
}